// round 1
// baseline (speedup 1.0000x reference)
#include <cuda_runtime.h>
#include <cuda_bf16.h>

// HANMeta: B=512, P=64, K=8, D=512, T=50000
// out[B*P, 2D] = concat(inputs[b,p], sum_k softmax_k(mask? <f, nbr_k> : -1e9)*mask * title[nt_k])

#define HM_B 512
#define HM_P 64
#define HM_K 8
#define HM_D 512
#define HM_ROWS (HM_B * HM_P)   // 32768
#define HM_BLOCK 128            // one float4 lane per thread covers D=512

__global__ __launch_bounds__(HM_BLOCK) void han_meta_kernel(
    const float* __restrict__ inputs,       // [B,P,D]
    const float* __restrict__ title,        // [T,D]
    const int*   __restrict__ nbr_batch,    // [B,P,K]
    const int*   __restrict__ nbr_job,      // [B,P,K]
    const int*   __restrict__ nbr_title,    // [B,P,K]
    const int*   __restrict__ nbr_mask,     // [B,P,K]
    float*       __restrict__ out)          // [B*P, 2D]
{
    const int row = blockIdx.x;             // b*P + p
    const int tid = threadIdx.x;            // 0..127 -> float4 lane

    const int idxbase = row * HM_K;

    // Load indices/masks (uniform per block -> broadcast loads)
    int mk[HM_K];
    long long nbr_off[HM_K];
    int nt[HM_K];
    #pragma unroll
    for (int k = 0; k < HM_K; k++) {
        mk[k] = nbr_mask[idxbase + k];
        int nb = nbr_batch[idxbase + k];
        int nj = nbr_job[idxbase + k];
        nbr_off[k] = ((long long)nb * HM_P + nj) * HM_D;
        nt[k] = nbr_title[idxbase + k];
    }

    // Focal embedding chunk
    const float4 f = reinterpret_cast<const float4*>(inputs + (long long)row * HM_D)[tid];

    // Masked dot-product partials: skip gather entirely when mask==0
    float part[HM_K];
    #pragma unroll
    for (int k = 0; k < HM_K; k++) {
        if (mk[k]) {
            float4 v = reinterpret_cast<const float4*>(inputs + nbr_off[k])[tid];
            part[k] = f.x * v.x + f.y * v.y + f.z * v.z + f.w * v.w;
        } else {
            part[k] = 0.0f;
        }
    }

    // Warp-level reduction of the 8-vector
    #pragma unroll
    for (int off = 16; off > 0; off >>= 1) {
        #pragma unroll
        for (int k = 0; k < HM_K; k++)
            part[k] += __shfl_xor_sync(0xffffffffu, part[k], off);
    }

    __shared__ float warp_sums[4][HM_K];
    const int warp = tid >> 5, lane = tid & 31;
    if (lane == 0) {
        #pragma unroll
        for (int k = 0; k < HM_K; k++) warp_sums[warp][k] = part[k];
    }
    __syncthreads();

    // Softmax weights (computed redundantly by every thread; mirrors reference
    // semantics exactly including the all-masked -> zero-row case)
    float w[HM_K];
    {
        float logit[HM_K];
        float m = -3.0e38f;
        #pragma unroll
        for (int k = 0; k < HM_K; k++) {
            float s = warp_sums[0][k] + warp_sums[1][k]
                    + warp_sums[2][k] + warp_sums[3][k];
            logit[k] = mk[k] ? s : -1e9f;
            m = fmaxf(m, logit[k]);
        }
        float sum = 0.0f;
        #pragma unroll
        for (int k = 0; k < HM_K; k++) {
            w[k] = __expf(logit[k] - m);
            sum += w[k];
        }
        float inv = 1.0f / sum;
        #pragma unroll
        for (int k = 0; k < HM_K; k++)
            w[k] = mk[k] ? (w[k] * inv) : 0.0f;
    }

    // Masked weighted sum of title embeddings (skip gather when mask==0)
    float4 acc = make_float4(0.f, 0.f, 0.f, 0.f);
    #pragma unroll
    for (int k = 0; k < HM_K; k++) {
        if (mk[k]) {
            float4 v = reinterpret_cast<const float4*>(title + (long long)nt[k] * HM_D)[tid];
            acc.x += w[k] * v.x;
            acc.y += w[k] * v.y;
            acc.z += w[k] * v.z;
            acc.w += w[k] * v.w;
        }
    }

    // Coalesced output: [focal | graph]
    float4* o = reinterpret_cast<float4*>(out + (long long)row * (2 * HM_D));
    o[tid] = f;
    o[HM_BLOCK + tid] = acc;
}

extern "C" void kernel_launch(void* const* d_in, const int* in_sizes, int n_in,
                              void* d_out, int out_size)
{
    const float* inputs    = (const float*)d_in[0];
    const float* title     = (const float*)d_in[1];
    const int*   nbr_batch = (const int*)  d_in[2];
    const int*   nbr_job   = (const int*)  d_in[3];
    const int*   nbr_title = (const int*)  d_in[4];
    const int*   nbr_mask  = (const int*)  d_in[5];
    float*       out       = (float*)d_out;

    han_meta_kernel<<<HM_ROWS, HM_BLOCK>>>(inputs, title, nbr_batch, nbr_job,
                                           nbr_title, nbr_mask, out);
}

// round 2
// speedup vs baseline: 1.1595x; 1.1595x over previous
#include <cuda_runtime.h>
#include <cuda_bf16.h>

// HANMeta: B=512, P=64, K=8, D=512, T=50000
// out[B*P, 2D] = concat(inputs[b,p], sum_k softmax_k(mask? <f,nbr_k> : -1e9)*mask * title[nt_k])

#define HM_B 512
#define HM_P 64
#define HM_K 8
#define HM_D 512
#define HM_ROWS (HM_B * HM_P)   // 32768
#define HM_BLOCK 128            // one float4 lane per thread covers D=512

__global__ __launch_bounds__(HM_BLOCK, 12) void han_meta_kernel(
    const float* __restrict__ inputs,       // [B,P,D]
    const float* __restrict__ title,        // [T,D]
    const int*   __restrict__ nbr_batch,    // [B,P,K]
    const int*   __restrict__ nbr_job,      // [B,P,K]
    const int*   __restrict__ nbr_title,    // [B,P,K]
    const int*   __restrict__ nbr_mask,     // [B,P,K]
    float*       __restrict__ out)          // [B*P, 2D]
{
    const int row = blockIdx.x;             // b*P + p
    const int tid = threadIdx.x;            // 0..127 -> float4 lane

    __shared__ __align__(16) int s_off[HM_K];   // neighbor row offset (floats)
    __shared__ __align__(16) int s_nt[HM_K];    // title row index
    __shared__ __align__(16) int s_mk[HM_K];    // mask
    __shared__ float s_ws[4][HM_K];             // per-warp dot partials

    // One cooperative index load per block (was: 32 broadcast LDGs per thread)
    if (tid < HM_K) {
        const int base = row * HM_K + tid;
        s_off[tid] = (nbr_batch[base] * HM_P + nbr_job[base]) * HM_D;  // < 2^25, int ok
        s_nt[tid]  = nbr_title[base];
        s_mk[tid]  = nbr_mask[base];
    }
    __syncthreads();

    // Focal embedding chunk
    const float4 f = reinterpret_cast<const float4*>(inputs + row * HM_D)[tid];

    // Vectorized broadcast reads of indices from shared
    const int4 mkv0 = *reinterpret_cast<const int4*>(&s_mk[0]);
    const int4 mkv1 = *reinterpret_cast<const int4*>(&s_mk[4]);
    const int4 ofv0 = *reinterpret_cast<const int4*>(&s_off[0]);
    const int4 ofv1 = *reinterpret_cast<const int4*>(&s_off[4]);
    const int mk[HM_K]  = {mkv0.x, mkv0.y, mkv0.z, mkv0.w, mkv1.x, mkv1.y, mkv1.z, mkv1.w};
    const int off[HM_K] = {ofv0.x, ofv0.y, ofv0.z, ofv0.w, ofv1.x, ofv1.y, ofv1.z, ofv1.w};

    // Masked dot-product partials: skip gather entirely when mask==0.
    // 8 independent loads in flight (MLP=8).
    float part[HM_K];
    #pragma unroll
    for (int k = 0; k < HM_K; k++) {
        part[k] = 0.0f;
        if (mk[k]) {
            float4 v = reinterpret_cast<const float4*>(inputs + off[k])[tid];
            part[k] = f.x * v.x + f.y * v.y + f.z * v.z + f.w * v.w;
        }
    }

    // Warp-level reduction of the 8-vector
    #pragma unroll
    for (int sh = 16; sh > 0; sh >>= 1) {
        #pragma unroll
        for (int k = 0; k < HM_K; k++)
            part[k] += __shfl_xor_sync(0xffffffffu, part[k], sh);
    }

    const int warp = tid >> 5, lane = tid & 31;
    if (lane == 0) {
        #pragma unroll
        for (int k = 0; k < HM_K; k++) s_ws[warp][k] = part[k];
    }
    __syncthreads();

    // Softmax weights (redundant per thread; mirrors reference semantics
    // exactly, including the all-masked -> zero-row case)
    float w[HM_K];
    {
        float logit[HM_K];
        float m = -3.0e38f;
        #pragma unroll
        for (int k = 0; k < HM_K; k++) {
            float s = s_ws[0][k] + s_ws[1][k] + s_ws[2][k] + s_ws[3][k];
            logit[k] = mk[k] ? s : -1e9f;
            m = fmaxf(m, logit[k]);
        }
        float sum = 0.0f;
        #pragma unroll
        for (int k = 0; k < HM_K; k++) {
            w[k] = __expf(logit[k] - m);
            sum += w[k];
        }
        const float inv = 1.0f / sum;
        #pragma unroll
        for (int k = 0; k < HM_K; k++)
            w[k] = mk[k] ? (w[k] * inv) : 0.0f;
    }

    // Vectorized broadcast read of title indices
    const int4 ntv0 = *reinterpret_cast<const int4*>(&s_nt[0]);
    const int4 ntv1 = *reinterpret_cast<const int4*>(&s_nt[4]);
    const int nt[HM_K] = {ntv0.x, ntv0.y, ntv0.z, ntv0.w, ntv1.x, ntv1.y, ntv1.z, ntv1.w};

    // Masked weighted sum of title embeddings (skip gather when mask==0)
    float4 acc = make_float4(0.f, 0.f, 0.f, 0.f);
    #pragma unroll
    for (int k = 0; k < HM_K; k++) {
        if (mk[k]) {
            float4 v = reinterpret_cast<const float4*>(title + nt[k] * HM_D)[tid];
            acc.x += w[k] * v.x;
            acc.y += w[k] * v.y;
            acc.z += w[k] * v.z;
            acc.w += w[k] * v.w;
        }
    }

    // Streaming (evict-first) stores: output is write-once, keep it out of
    // the title/inputs L2 working set.
    float4* o = reinterpret_cast<float4*>(out + row * (2 * HM_D));
    __stcs(o + tid, f);
    __stcs(o + HM_BLOCK + tid, acc);
}

extern "C" void kernel_launch(void* const* d_in, const int* in_sizes, int n_in,
                              void* d_out, int out_size)
{
    const float* inputs    = (const float*)d_in[0];
    const float* title     = (const float*)d_in[1];
    const int*   nbr_batch = (const int*)  d_in[2];
    const int*   nbr_job   = (const int*)  d_in[3];
    const int*   nbr_title = (const int*)  d_in[4];
    const int*   nbr_mask  = (const int*)  d_in[5];
    float*       out       = (float*)d_out;

    han_meta_kernel<<<HM_ROWS, HM_BLOCK>>>(inputs, title, nbr_batch, nbr_job,
                                           nbr_title, nbr_mask, out);
}